// round 10
// baseline (speedup 1.0000x reference)
#include <cuda_runtime.h>
#include <cuda_bf16.h>
#include <stdint.h>

#define N_ROWS 32768
#define K_CODES 8192
#define D_DIM 256
#define THETA 5e-4f
#define ROWCAP 16
#define SW (1.0f/1040384.0f)      // w scale: |w| <= 1/8192 -> wq in [-127,127]
#define INV_SW 1040384.0f

// dp4a kernel smem: xs int32[64][132] (33792B) + ws int2[64][64] (32768B)
#define OFF_XS 0
#define XS_STRIDE 132
#define OFF_WS 33792
#define SMEM_TOTAL 66560

__device__ char   g_xq[N_ROWS * D_DIM];
__device__ char   g_wq[K_CODES * D_DIM];
__device__ float  g_wsq[K_CODES];
__device__ float  g_xsq[N_ROWS];
__device__ float  g_xscale[N_ROWS];
__device__ int    g_ccnt[N_ROWS];
__device__ int    g_clist[N_ROWS * ROWCAP];
__device__ int    g_idx[N_ROWS];
__device__ double g_part[4096];

// ---- launch #1: per-row xsq (EXACT formula proven rel_err 0.0) + maxabs/scale
__global__ __launch_bounds__(256)
void rowstat_kernel(const float* __restrict__ x) {
    int row = blockIdx.x * 256 + threadIdx.x;
    if (row >= N_ROWS) return;
    const float4* p = (const float4*)(x + (size_t)row * D_DIM);
    float s0 = 0.f, s1 = 0.f, s2 = 0.f, s3 = 0.f;
    float mx = 0.f;
    #pragma unroll 8
    for (int c = 0; c < D_DIM / 4; ++c) {
        float4 v = __ldg(p + c);
        s0 = __fmaf_rn(v.x, v.x, s0); s1 = __fmaf_rn(v.y, v.y, s1);
        s2 = __fmaf_rn(v.z, v.z, s2); s3 = __fmaf_rn(v.w, v.w, s3);
        mx = fmaxf(mx, fmaxf(fmaxf(fabsf(v.x), fabsf(v.y)),
                             fmaxf(fabsf(v.z), fabsf(v.w))));
    }
    g_xsq[row] = __fadd_rn(__fadd_rn(s0, s1), __fadd_rn(s2, s3));
    g_xscale[row] = mx / 127.0f;
}

// ---- launch #2: quantize x with per-row scale
__global__ __launch_bounds__(256)
void quantx_kernel(const float* __restrict__ x) {
    int i = blockIdx.x * 256 + threadIdx.x;        // float4 index
    if (i >= N_ROWS * D_DIM / 4) return;
    int row = i >> 6;
    float sc = g_xscale[row];
    float inv = (sc > 0.f) ? (1.0f / sc) : 0.f;
    float4 v = __ldg((const float4*)x + i);
    char4 q;
    q.x = (char)__float2int_rn(v.x * inv);
    q.y = (char)__float2int_rn(v.y * inv);
    q.z = (char)__float2int_rn(v.z * inv);
    q.w = (char)__float2int_rn(v.w * inv);
    ((char4*)g_xq)[i] = q;
}

// ---- launch #3: per-row wsq (EXACT formula) + quantize w (fixed scale)
__global__ __launch_bounds__(256)
void prepw_kernel(const float* __restrict__ w) {
    int row = blockIdx.x * 256 + threadIdx.x;
    if (row >= K_CODES) return;
    const float4* p = (const float4*)(w + (size_t)row * D_DIM);
    char4* dst = (char4*)(g_wq + (size_t)row * D_DIM);
    float s0 = 0.f, s1 = 0.f, s2 = 0.f, s3 = 0.f;
    #pragma unroll 8
    for (int c = 0; c < D_DIM / 4; ++c) {
        float4 v = __ldg(p + c);
        s0 = __fmaf_rn(v.x, v.x, s0); s1 = __fmaf_rn(v.y, v.y, s1);
        s2 = __fmaf_rn(v.z, v.z, s2); s3 = __fmaf_rn(v.w, v.w, s3);
        char4 q;
        q.x = (char)__float2int_rn(v.x * INV_SW);
        q.y = (char)__float2int_rn(v.y * INV_SW);
        q.z = (char)__float2int_rn(v.z * INV_SW);
        q.w = (char)__float2int_rn(v.w * INV_SW);
        dst[c] = q;
    }
    g_wsq[row] = __fadd_rn(__fadd_rn(s0, s1), __fadd_rn(s2, s3));
}

// ---- launch #4 (PROFILED): dp4a distance screen + fused argmin candidates
__global__ __launch_bounds__(256, 1)
void vq_dp4a_kernel() {
    extern __shared__ char sm[];
    int*  xs  = (int*)(sm + OFF_XS);     // [k 0..63][row 0..127] stride 132
    int2* ws2 = (int2*)(sm + OFF_WS);    // [k 0..63][pair 0..63]

    const int tid = threadIdx.x;
    const int tx = tid & 15, ty = tid >> 4;
    const int r0 = blockIdx.x * 128;

    // x transpose-load: g_xq[row][256] -> xs[k][row]
    {
        int row = tid & 127, kg = (tid >> 7) * 32;
        const int4* src = (const int4*)(g_xq + (size_t)(r0 + row) * D_DIM);
        #pragma unroll
        for (int u = 0; u < 8; ++u) {
            int4 v = __ldg(src + (kg >> 2) + u);
            int k = kg + u * 4;
            xs[(k + 0) * XS_STRIDE + row] = v.x;
            xs[(k + 1) * XS_STRIDE + row] = v.y;
            xs[(k + 2) * XS_STRIDE + row] = v.z;
            xs[(k + 3) * XS_STRIDE + row] = v.w;
        }
    }

    float m2s[8];
    #pragma unroll
    for (int e = 0; e < 8; ++e)
        m2s[e] = -2.0f * SW * g_xscale[r0 + ty * 8 + e];

    // screening state: 3 stale-recycled slots per (thread,row)
    float bv[8], s0v[8], s1v[8], s2v[8];
    int s0i[8], s1i[8], s2i[8], ovf[8];
    #pragma unroll
    for (int e = 0; e < 8; ++e) {
        bv[e] = 3.4e38f;
        s0v[e] = s1v[e] = s2v[e] = 3.4e38f;
        s0i[e] = s1i[e] = s2i[e] = 0;
        ovf[e] = 0;
    }

    for (int t = 0; t < K_CODES / 128; ++t) {
        __syncthreads();   // previous tile's smem reads complete
        // w tile load: g_wq[col][256] -> ws2[k][col>>1].{x|y}
        {
            int c = tid & 127, kg = (tid >> 7) * 32;
            const int4* src = (const int4*)(g_wq + (size_t)(t * 128 + c) * D_DIM);
            int* w32 = (int*)ws2;
            int base = (c >> 1) * 2 + (c & 1);
            #pragma unroll
            for (int u = 0; u < 8; ++u) {
                int4 v = __ldg(src + (kg >> 2) + u);
                int k = kg + u * 4;
                w32[(k + 0) * 128 + base] = v.x;
                w32[(k + 1) * 128 + base] = v.y;
                w32[(k + 2) * 128 + base] = v.z;
                w32[(k + 3) * 128 + base] = v.w;
            }
        }
        __syncthreads();

        int acc[8][8];
        #pragma unroll
        for (int r = 0; r < 8; ++r)
            #pragma unroll
            for (int c = 0; c < 8; ++c) acc[r][c] = 0;

        #pragma unroll 4
        for (int k = 0; k < 64; ++k) {
            int4 xa = *(const int4*)&xs[k * XS_STRIDE + ty * 8];
            int4 xb = *(const int4*)&xs[k * XS_STRIDE + ty * 8 + 4];
            int2 w0 = ws2[k * 64 + tx];
            int2 w1 = ws2[k * 64 + tx + 16];
            int2 w2v = ws2[k * 64 + tx + 32];
            int2 w3 = ws2[k * 64 + tx + 48];
            int xr[8] = {xa.x, xa.y, xa.z, xa.w, xb.x, xb.y, xb.z, xb.w};
            int wc[8] = {w0.x, w0.y, w1.x, w1.y, w2v.x, w2v.y, w3.x, w3.y};
            #pragma unroll
            for (int r = 0; r < 8; ++r)
                #pragma unroll
                for (int c = 0; c < 8; ++c)
                    acc[r][c] = __dp4a(xr[r], wc[c], acc[r][c]);
        }

        // epilogue: screen dv = wsq - 2*sx*sw*acc
        #pragma unroll
        for (int cc = 0; cc < 4; ++cc) {
            int col0 = t * 128 + 2 * tx + 32 * cc;
            float2 wsq2 = __ldg((const float2*)&g_wsq[col0]);
            #pragma unroll
            for (int e = 0; e < 8; ++e) {
                #pragma unroll
                for (int h = 0; h < 2; ++h) {
                    float dv = __fmaf_rn(m2s[e], (float)acc[e][cc * 2 + h],
                                         h ? wsq2.y : wsq2.x);
                    if (dv < bv[e] + THETA) {
                        if (dv < bv[e]) bv[e] = dv;
                        float thr = bv[e] + THETA;
                        int col = col0 + h;
                        if      (s0v[e] >= thr) { s0v[e] = dv; s0i[e] = col; }
                        else if (s1v[e] >= thr) { s1v[e] = dv; s1i[e] = col; }
                        else if (s2v[e] >= thr) { s2v[e] = dv; s2i[e] = col; }
                        else ovf[e] = 1;
                    }
                }
            }
        }
    }
    __syncthreads();

    // merge overlay: per (row, tx) 24B record of 3 slots
    #pragma unroll
    for (int e = 0; e < 8; ++e) {
        int row = ty * 8 + e;
        float* mg = (float*)(sm + (size_t)(row * 16 + tx) * 24);
        mg[0] = ovf[e] ? -1e38f : s0v[e]; ((int*)mg)[1] = s0i[e];
        mg[2] = s1v[e];                   ((int*)mg)[3] = s1i[e];
        mg[4] = s2v[e];                   ((int*)mg)[5] = s2i[e];
    }
    __syncthreads();

    if (tid < 128) {
        float rm = 3.4e38f;
        bool rowovf = false;
        for (int o = 0; o < 16; ++o) {
            const float* mg = (const float*)(sm + (size_t)(tid * 16 + o) * 24);
            #pragma unroll
            for (int s = 0; s < 3; ++s) {
                float v = mg[2 * s];
                if (v < -1e30f) rowovf = true;
                else rm = fminf(rm, v);
            }
        }
        int list[ROWCAP];
        int n = 0;
        for (int o = 0; o < 16; ++o) {
            const float* mg = (const float*)(sm + (size_t)(tid * 16 + o) * 24);
            #pragma unroll
            for (int s = 0; s < 3; ++s) {
                float v = mg[2 * s];
                if (v > -1e30f && v < rm + THETA) {
                    if (n < ROWCAP) list[n++] = ((const int*)mg)[2 * s + 1];
                    else rowovf = true;
                }
            }
        }
        g_ccnt[r0 + tid] = rowovf ? (ROWCAP + 1) : n;
        for (int e = 0; e < n; ++e)
            g_clist[(size_t)(r0 + tid) * ROWCAP + e] = list[e];
    }
}

// ---- launch #5: exact rescue, bit-matching ref fp32 sequence (proven)
__global__ __launch_bounds__(256)
void rescue_kernel(const float* __restrict__ x, const float* __restrict__ w,
                   float* __restrict__ idxo) {
    int wid = threadIdx.x >> 5, lane = threadIdx.x & 31;
    int row = blockIdx.x * 8 + wid;
    if (row >= N_ROWS) return;
    int cnt = g_ccnt[row];
    if (cnt == 1) {
        if (lane == 0) {
            int bi = g_clist[(size_t)row * ROWCAP];
            g_idx[row] = bi;
            if (idxo) idxo[row] = (float)bi;
        }
        return;
    }
    float xsq = g_xsq[row];
    const float4* xr = (const float4*)(x + (size_t)row * D_DIM);
    float bestv = 3.4e38f;
    int besti = 0x7fffffff;
    auto exact = [&](int col) -> float {
        const float4* wr = (const float4*)(w + (size_t)col * D_DIM);
        float g = 0.f;
        #pragma unroll 8
        for (int q = 0; q < 64; ++q) {   // strictly sequential k order
            float4 xv = xr[q];
            float4 wv = __ldg(wr + q);
            g = __fmaf_rn(xv.x, wv.x, g); g = __fmaf_rn(xv.y, wv.y, g);
            g = __fmaf_rn(xv.z, wv.z, g); g = __fmaf_rn(xv.w, wv.w, g);
        }
        return __fadd_rn(__fsub_rn(xsq, __fmul_rn(2.f, g)), __ldg(&g_wsq[col]));
    };
    if (cnt <= ROWCAP) {
        if (lane < cnt) {
            int cix = g_clist[(size_t)row * ROWCAP + lane];
            bestv = exact(cix);
            besti = cix;
        }
    } else {
        for (int base = 0; base < K_CODES; base += 32) {
            int cix = base + lane;
            float dv = exact(cix);
            if (dv < bestv || (dv == bestv && cix < besti)) { bestv = dv; besti = cix; }
        }
    }
    #pragma unroll
    for (int mk = 16; mk > 0; mk >>= 1) {
        float vo = __shfl_xor_sync(0xffffffffu, bestv, mk);
        int io = __shfl_xor_sync(0xffffffffu, besti, mk);
        if (vo < bestv || (vo == bestv && io < besti)) { bestv = vo; besti = io; }
    }
    if (lane == 0) {
        g_idx[row] = besti;
        if (idxo) idxo[row] = (float)besti;
    }
}

// ---- launch #6: straight-through output + loss partials (proven)
__global__ __launch_bounds__(256)
void loss_gather_kernel(const float* __restrict__ x, const float* __restrict__ w,
                        float* __restrict__ qst) {
    __shared__ double sred[256];
    int tid = threadIdx.x;
    double s = 0.0;
    size_t base = (size_t)blockIdx.x * 2048;
    #pragma unroll
    for (int i = 0; i < 2; ++i) {
        size_t e = base + (size_t)tid * 4 + (size_t)i * 1024;
        int row = (int)(e >> 8);
        int d = (int)(e & 255);
        int idx = g_idx[row];
        float4 xv = *(const float4*)(x + e);
        float4 qv = __ldg((const float4*)(w + (size_t)idx * D_DIM + d));
        float4 o;
        o.x = __fadd_rn(xv.x, __fsub_rn(qv.x, xv.x));
        o.y = __fadd_rn(xv.y, __fsub_rn(qv.y, xv.y));
        o.z = __fadd_rn(xv.z, __fsub_rn(qv.z, xv.z));
        o.w = __fadd_rn(xv.w, __fsub_rn(qv.w, xv.w));
        *(float4*)(qst + e) = o;
        float dx;
        dx = __fsub_rn(xv.x, qv.x); s += (double)__fmul_rn(dx, dx);
        dx = __fsub_rn(xv.y, qv.y); s += (double)__fmul_rn(dx, dx);
        dx = __fsub_rn(xv.z, qv.z); s += (double)__fmul_rn(dx, dx);
        dx = __fsub_rn(xv.w, qv.w); s += (double)__fmul_rn(dx, dx);
    }
    sred[tid] = s;
    __syncthreads();
    for (int st = 128; st > 0; st >>= 1) {
        if (tid < st) sred[tid] += sred[tid + st];
        __syncthreads();
    }
    if (tid == 0) g_part[blockIdx.x] = sred[0];
}

// ---- launch #7: final loss scalars
__global__ __launch_bounds__(256)
void finalize_kernel(float* __restrict__ sc) {
    __shared__ double sred[256];
    int tid = threadIdx.x;
    double s = 0.0;
    for (int j = tid; j < 4096; j += 256) s += g_part[j];
    sred[tid] = s;
    __syncthreads();
    for (int st = 128; st > 0; st >>= 1) {
        if (tid < st) sred[tid] += sred[tid + st];
        __syncthreads();
    }
    if (tid == 0 && sc) {
        double mean = sred[0] / (double)((size_t)N_ROWS * D_DIM);
        float M = (float)mean;
        float commit = __fmul_rn(M, 0.25f);
        sc[0] = commit;
        sc[1] = M;
        sc[2] = __fadd_rn(commit, M);
    }
}

extern "C" void kernel_launch(void* const* d_in, const int* in_sizes, int n_in,
                              void* d_out, int out_size) {
    const float* x = (const float*)d_in[0];
    const float* w = (const float*)d_in[1];
    if (n_in >= 2 && in_sizes[0] == K_CODES * D_DIM && in_sizes[1] == N_ROWS * D_DIM) {
        const float* t = x; x = w; w = t;
    }

    float* out = (float*)d_out;
    const int ND = N_ROWS * D_DIM;
    float* qst = out;
    float* idxo = (out_size >= ND + N_ROWS) ? out + ND : nullptr;
    float* sc = (out_size >= ND + N_ROWS + 3) ? out + ND + N_ROWS : nullptr;

    static int setup = 0;
    if (!setup) {
        cudaFuncSetAttribute(vq_dp4a_kernel,
                             cudaFuncAttributeMaxDynamicSharedMemorySize, SMEM_TOTAL);
        setup = 1;
    }

    rowstat_kernel<<<N_ROWS / 256, 256>>>(x);                       // #1
    quantx_kernel<<<(N_ROWS * D_DIM / 4) / 256, 256>>>(x);          // #2
    prepw_kernel<<<K_CODES / 256, 256>>>(w);                        // #3
    vq_dp4a_kernel<<<N_ROWS / 128, 256, SMEM_TOTAL>>>();            // #4 (profiled)
    rescue_kernel<<<N_ROWS / 8, 256>>>(x, w, idxo);                 // #5
    loss_gather_kernel<<<4096, 256>>>(x, w, qst);                   // #6
    finalize_kernel<<<1, 256>>>(sc);                                // #7
}

// round 11
// speedup vs baseline: 22.8654x; 22.8654x over previous
#include <cuda_runtime.h>
#include <cuda_bf16.h>
#include <stdint.h>

typedef unsigned long long ull;

#define N_ROWS 32768
#define K_CODES 8192
#define D_DIM 256
#define SPLITS 4
#define KSPLIT (K_CODES / SPLITS)   // 2048 cols per block
#define RPB 128                     // rows per block
#define NCHUNK 64                   // 64-d chunks per block (16 tiles x 4)
#define SXR 260                     // xs row stride (floats)
#define OFF_WS 133120               // byte offset of w smem (after xs)
#define SMEM_BYTES (133120 + 65536) // xs 128x260x4 + ws 2x64x64x8 = 198656

__device__ ull    g_wt[K_CODES * D_DIM / 2];  // pre-paired w: [gchunk][dl][pr]
__device__ float  g_wsq[K_CODES];
__device__ float  g_xsq[N_ROWS];
__device__ float  g_cand_val[SPLITS * N_ROWS];
__device__ int    g_cand_idx[SPLITS * N_ROWS];
__device__ int    g_idx[N_ROWS];
__device__ double g_part[4096];

__device__ __forceinline__ ull fma2(ull a, ull b, ull c) {
    ull d;
    asm("fma.rn.f32x2 %0, %1, %2, %3;" : "=l"(d) : "l"(a), "l"(b), "l"(c));
    return d;
}
__device__ __forceinline__ ull pack2(float a, float b) {
    ull r;
    asm("mov.b64 %0, {%1, %2};" : "=l"(r) : "f"(a), "f"(b));
    return r;
}
__device__ __forceinline__ void unpack2(ull v, float& lo, float& hi) {
    asm("mov.b64 {%0, %1}, %2;" : "=f"(lo), "=f"(hi) : "l"(v));
}
__device__ __forceinline__ void cp16(uint32_t dst, const void* src) {
    asm volatile("cp.async.cg.shared.global [%0], [%1], 16;" :: "r"(dst), "l"(src));
}

// ---- launch #1/#2: per-row sum of squares (argmin-safe in any fp32 order)
__global__ __launch_bounds__(256)
void rowsq_kernel(const float* __restrict__ src, int nrows, int which) {
    int row = blockIdx.x * 256 + threadIdx.x;
    if (row >= nrows) return;
    const float4* p = (const float4*)(src + (size_t)row * D_DIM);
    float s0 = 0.f, s1 = 0.f, s2 = 0.f, s3 = 0.f;
    #pragma unroll 8
    for (int c = 0; c < D_DIM / 4; ++c) {
        float4 v = __ldg(p + c);
        s0 = __fmaf_rn(v.x, v.x, s0); s1 = __fmaf_rn(v.y, v.y, s1);
        s2 = __fmaf_rn(v.z, v.z, s2); s3 = __fmaf_rn(v.w, v.w, s3);
    }
    float r = __fadd_rn(__fadd_rn(s0, s1), __fadd_rn(s2, s3));
    if (which == 0) g_wsq[row] = r; else g_xsq[row] = r;
}

// ---- launch #3: pre-pair w into f32x2 chunk layout
// g_wt[((t*4+c)*64 + dl)*64 + pr] = pack2(w[t*128+2pr][c*64+dl], w[t*128+2pr+1][...])
__global__ __launch_bounds__(256)
void prep_wt_kernel(const float* __restrict__ w) {
    int i = blockIdx.x * 256 + threadIdx.x;      // 0 .. 1048575
    int pr = i & 63;
    int dl = (i >> 6) & 63;
    int c  = (i >> 12) & 3;
    int t  = i >> 14;
    size_t base = (size_t)(t * 128 + 2 * pr) * D_DIM + c * 64 + dl;
    float a = __ldg(w + base);
    float b = __ldg(w + base + D_DIM);
    g_wt[i] = pack2(a, b);
}

// ---- launch #4 (PROFILED): exact-fp32 fused dist2 argmin, FFMA2 mainloop
// Block: 128 rows x 2048 codes (one K-split). Thread tile 8 rows x 8 cols.
__global__ __launch_bounds__(256, 1)
void vq_ffma2_kernel(const float* __restrict__ x)
{
    extern __shared__ float sm[];
    float* xs = sm;                              // [128 rows][260]
    ull* ws = (ull*)((char*)sm + OFF_WS);        // [2][64 dl][64 pr]

    const int tid = threadIdx.x;
    const int tx = tid & 15, ty = tid >> 4;
    const int r0 = blockIdx.x * RPB;
    const int chunkBase = blockIdx.y * NCHUNK;   // global chunk index base
    const int ksBase = blockIdx.y * KSPLIT;
    const int xoff = (ty & 1) * 4;               // x bank de-conflict swizzle

    // xs via cp.async: natural layout + 16B XOR swizzle per 8-row group (r4-proven)
    #pragma unroll
    for (int i = 0; i < 32; ++i) {
        int e = i * 256 + tid;
        int row = e >> 6, g = e & 63;
        uint32_t dst = (uint32_t)__cvta_generic_to_shared(
            xs + row * SXR + ((g ^ ((row >> 3) & 1)) << 2));
        cp16(dst, x + (size_t)(r0 + row) * D_DIM + g * 4);
    }
    asm volatile("cp.async.commit_group;" ::: "memory");

    auto loadW = [&](int m) {                    // one 32KB chunk, fully coalesced
        const ull* src = g_wt + (size_t)(chunkBase + m) * 4096;
        uint32_t dstb = (uint32_t)__cvta_generic_to_shared(ws + (m & 1) * 4096);
        #pragma unroll
        for (int i = 0; i < 8; ++i) {
            int e = i * 256 + tid;
            cp16(dstb + e * 16, src + e * 2);
        }
        asm volatile("cp.async.commit_group;" ::: "memory");
    };
    loadW(0);
    loadW(1);

    float xsqr[8], bestv[8];
    int besti[8];
    #pragma unroll
    for (int r = 0; r < 8; ++r) {
        xsqr[r] = g_xsq[r0 + ty * 8 + r];
        bestv[r] = 3.4e38f;
        besti[r] = 0;
    }

    ull acc[8][4];
    const float* xrow = xs + (ty * 8) * SXR;

    for (int m = 0; m < NCHUNK; ++m) {
        const int ch = m & 3;
        if (m < NCHUNK - 2) asm volatile("cp.async.wait_group 1;" ::: "memory");
        else                asm volatile("cp.async.wait_group 0;" ::: "memory");
        __syncthreads();

        if (ch == 0) {
            #pragma unroll
            for (int r = 0; r < 8; ++r)
                #pragma unroll
                for (int j = 0; j < 4; ++j) acc[r][j] = 0ull;
        }

        const ull* wp = ws + (m & 1) * 4096 + tx;
        const int dbase = ch * 64;
        #pragma unroll 4
        for (int dl = 0; dl < 64; ++dl) {
            ull wv0 = wp[dl * 64];
            ull wv1 = wp[dl * 64 + 16];
            ull wv2 = wp[dl * 64 + 32];
            ull wv3 = wp[dl * 64 + 48];
            const float* xp = xrow + ((dbase + dl) ^ xoff);
            #pragma unroll
            for (int r = 0; r < 8; ++r) {
                float xv = xp[r * SXR];
                ull px = pack2(xv, xv);
                acc[r][0] = fma2(px, wv0, acc[r][0]);
                acc[r][1] = fma2(px, wv1, acc[r][1]);
                acc[r][2] = fma2(px, wv2, acc[r][2]);
                acc[r][3] = fma2(px, wv3, acc[r][3]);
            }
        }

        if (ch == 3) {
            // epilogue: exact ref op sequence; strict-less keeps first index
            const int cb = ksBase + (m >> 2) * 128;
            #pragma unroll
            for (int j = 0; j < 4; ++j) {
                int col0 = cb + 2 * (tx + 16 * j);
                float w0 = __ldg(&g_wsq[col0]);
                float w1 = __ldg(&g_wsq[col0 + 1]);
                #pragma unroll
                for (int r = 0; r < 8; ++r) {
                    float glo, ghi;
                    unpack2(acc[r][j], glo, ghi);
                    float dv = __fadd_rn(__fsub_rn(xsqr[r], __fmul_rn(2.0f, glo)), w0);
                    if (dv < bestv[r]) { bestv[r] = dv; besti[r] = col0; }
                    dv = __fadd_rn(__fsub_rn(xsqr[r], __fmul_rn(2.0f, ghi)), w1);
                    if (dv < bestv[r]) { bestv[r] = dv; besti[r] = col0 + 1; }
                }
            }
        }
        __syncthreads();
        if (m + 2 < NCHUNK) loadW(m + 2);
    }

    // reduce over the 16 tx lanes, lexicographic (val, idx)
    #pragma unroll
    for (int r = 0; r < 8; ++r) {
        float v = bestv[r];
        int bi = besti[r];
        #pragma unroll
        for (int msk = 8; msk > 0; msk >>= 1) {
            float vo = __shfl_xor_sync(0xffffffffu, v, msk);
            int io = __shfl_xor_sync(0xffffffffu, bi, msk);
            if (vo < v || (vo == v && io < bi)) { v = vo; bi = io; }
        }
        if (tx == 0) {
            int slot = blockIdx.y * N_ROWS + r0 + ty * 8 + r;
            g_cand_val[slot] = v;
            g_cand_idx[slot] = bi;
        }
    }
}

// ---- launch #5: merge SPLITS candidates per row (ascending K, strict-less)
__global__ __launch_bounds__(256)
void combine_kernel(float* __restrict__ idx_out)
{
    int row = blockIdx.x * 256 + threadIdx.x;
    if (row >= N_ROWS) return;
    float bv = g_cand_val[row];
    int bi = g_cand_idx[row];
    #pragma unroll
    for (int s = 1; s < SPLITS; ++s) {
        float v = g_cand_val[s * N_ROWS + row];
        int i = g_cand_idx[s * N_ROWS + row];
        if (v < bv) { bv = v; bi = i; }
    }
    g_idx[row] = bi;
    if (idx_out) idx_out[row] = (float)bi;
}

// ---- launch #6: straight-through output + loss partials
__global__ __launch_bounds__(256)
void loss_gather_kernel(const float* __restrict__ x, const float* __restrict__ w,
                        float* __restrict__ qst)
{
    __shared__ double sred[256];
    int tid = threadIdx.x;
    double s = 0.0;
    size_t base = (size_t)blockIdx.x * 2048;
    #pragma unroll
    for (int i = 0; i < 2; ++i) {
        size_t e = base + (size_t)tid * 4 + (size_t)i * 1024;
        int row = (int)(e >> 8);
        int d = (int)(e & 255);
        int idx = g_idx[row];
        float4 xv = *(const float4*)(x + e);
        float4 qv = __ldg((const float4*)(w + (size_t)idx * D_DIM + d));
        float4 o;
        o.x = __fadd_rn(xv.x, __fsub_rn(qv.x, xv.x));
        o.y = __fadd_rn(xv.y, __fsub_rn(qv.y, xv.y));
        o.z = __fadd_rn(xv.z, __fsub_rn(qv.z, xv.z));
        o.w = __fadd_rn(xv.w, __fsub_rn(qv.w, xv.w));
        *(float4*)(qst + e) = o;
        float dx;
        dx = __fsub_rn(xv.x, qv.x); s += (double)__fmul_rn(dx, dx);
        dx = __fsub_rn(xv.y, qv.y); s += (double)__fmul_rn(dx, dx);
        dx = __fsub_rn(xv.z, qv.z); s += (double)__fmul_rn(dx, dx);
        dx = __fsub_rn(xv.w, qv.w); s += (double)__fmul_rn(dx, dx);
    }
    sred[tid] = s;
    __syncthreads();
    for (int st = 128; st > 0; st >>= 1) {
        if (tid < st) sred[tid] += sred[tid + st];
        __syncthreads();
    }
    if (tid == 0) g_part[blockIdx.x] = sred[0];
}

// ---- launch #7: final loss scalars
__global__ __launch_bounds__(256)
void finalize_kernel(float* __restrict__ sc)
{
    __shared__ double sred[256];
    int tid = threadIdx.x;
    double s = 0.0;
    for (int j = tid; j < 4096; j += 256) s += g_part[j];
    sred[tid] = s;
    __syncthreads();
    for (int st = 128; st > 0; st >>= 1) {
        if (tid < st) sred[tid] += sred[tid + st];
        __syncthreads();
    }
    if (tid == 0 && sc) {
        double mean = sred[0] / (double)((size_t)N_ROWS * D_DIM);
        float M = (float)mean;
        float commit = __fmul_rn(M, 0.25f);
        sc[0] = commit;
        sc[1] = M;
        sc[2] = __fadd_rn(commit, M);
    }
}

extern "C" void kernel_launch(void* const* d_in, const int* in_sizes, int n_in,
                              void* d_out, int out_size)
{
    const float* x = (const float*)d_in[0];
    const float* w = (const float*)d_in[1];
    if (n_in >= 2 && in_sizes[0] == K_CODES * D_DIM && in_sizes[1] == N_ROWS * D_DIM) {
        const float* t = x; x = w; w = t;
    }

    float* out = (float*)d_out;
    const int ND = N_ROWS * D_DIM;
    float* qst = out;
    float* idxo = (out_size >= ND + N_ROWS) ? out + ND : nullptr;
    float* sc = (out_size >= ND + N_ROWS + 3) ? out + ND + N_ROWS : nullptr;

    static int setup = 0;
    if (!setup) {
        cudaFuncSetAttribute(vq_ffma2_kernel,
                             cudaFuncAttributeMaxDynamicSharedMemorySize, SMEM_BYTES);
        setup = 1;
    }

    rowsq_kernel<<<K_CODES / 256, 256>>>(w, K_CODES, 0);                 // #1
    rowsq_kernel<<<N_ROWS / 256, 256>>>(x, N_ROWS, 1);                   // #2
    prep_wt_kernel<<<(K_CODES * D_DIM / 2) / 256, 256>>>(w);             // #3
    vq_ffma2_kernel<<<dim3(N_ROWS / RPB, SPLITS), 256, SMEM_BYTES>>>(x); // #4 (profiled)
    combine_kernel<<<N_ROWS / 256, 256>>>(idxo);                         // #5
    loss_gather_kernel<<<4096, 256>>>(x, w, qst);                        // #6
    finalize_kernel<<<1, 256>>>(sc);                                     // #7
}